// round 9
// baseline (speedup 1.0000x reference)
#include <cuda_runtime.h>

// AttentionOptimizer: out = spins - LR*(grads + SMOOTH*g_smooth) + noise
// g_smooth = conv3(u)/conv3(v),  u = g*exp(-BETA*|g|), v = exp(-BETA*|g|),
// separable per-axis kernel w[d] = exp(-0.0125*(d*2/19)^2) = exp(-0.05 d^2/361).
//
// R9 = R8 + tail/load shaves:
//   - grads[gi] deleted (it equals gc[yo], already in registers)
//   - epilogue base (s + n - 0.05*g) precomputed under phase-1 MUFU latency
//   - 4 accumulators in phase 1 (5-deep fma2 chains; MUFU never gated)

#define LLAT 20
#define PLANE 400                 // LLAT*LLAT
#define NPTS 8000                 // LLAT^3
#define NEG2_LOG2E 2.8853900817779268f   // 2*log2(e)

// CW2[i] = {w,w} with w = exp(-0.05*(i-19)^2/361)  (hand-evaluated)
__constant__ float2 CW2[2 * LLAT - 1] = {
    {0.9512294245f, 0.9512294245f}, {0.9561166621f, 0.9561166621f},
    {0.9607628249f, 0.9607628249f}, {0.9651641734f, 0.9651641734f},
    {0.9693171397f, 0.9693171397f}, {0.9732183487f, 0.9732183487f},
    {0.9768646216f, 0.9768646216f}, {0.9802529795f, 0.9802529795f},
    {0.9833806481f, 0.9833806481f}, {0.9862450604f, 0.9862450604f},
    {0.9888438596f, 0.9888438596f}, {0.9911749058f, 0.9911749058f},
    {0.9932362740f, 0.9932362740f}, {0.9950262606f, 0.9950262606f},
    {0.9965433840f, 0.9965433840f}, {0.9977863872f, 0.9977863872f},
    {0.9987542392f, 0.9987542392f}, {0.9994461368f, 0.9994461368f},
    {0.9998615054f, 0.9998615054f}, {1.0000000000f, 1.0000000000f},
    {0.9998615054f, 0.9998615054f}, {0.9994461368f, 0.9994461368f},
    {0.9987542392f, 0.9987542392f}, {0.9977863872f, 0.9977863872f},
    {0.9965433840f, 0.9965433840f}, {0.9950262606f, 0.9950262606f},
    {0.9932362740f, 0.9932362740f}, {0.9911749058f, 0.9911749058f},
    {0.9888438596f, 0.9888438596f}, {0.9862450604f, 0.9862450604f},
    {0.9833806481f, 0.9833806481f}, {0.9802529795f, 0.9802529795f},
    {0.9768646216f, 0.9768646216f}, {0.9732183487f, 0.9732183487f},
    {0.9693171397f, 0.9693171397f}, {0.9651641734f, 0.9651641734f},
    {0.9607628249f, 0.9607628249f}, {0.9561166621f, 0.9561166621f},
    {0.9512294245f, 0.9512294245f}
};

// Packed f32x2 FMA (sm_103a): d = a*b + c on both lanes.
static __device__ __forceinline__ float2 fma2(float2 a, float2 b, float2 c) {
    float2 d;
    asm("fma.rn.f32x2 %0, %1, %2, %3;"
        : "=l"(*reinterpret_cast<unsigned long long*>(&d))
        : "l"(*reinterpret_cast<unsigned long long*>(&a)),
          "l"(*reinterpret_cast<unsigned long long*>(&b)),
          "l"(*reinterpret_cast<unsigned long long*>(&c)));
    return d;
}

static __device__ __forceinline__ float2 add2(float2 a, float2 b) {
    return make_float2(a.x + b.x, a.y + b.y);
}

__global__ void __launch_bounds__(PLANE, 1)
attn_opt_fused(const float* __restrict__ grads,
               const float* __restrict__ spins,
               const float* __restrict__ noise,
               float* __restrict__ out)
{
    __shared__ float2 V[PLANE];
    __shared__ float2 T[PLANE];
    __shared__ float2 w2[2 * LLAT - 1];   // smem copy for per-thread indices

    const int t  = threadIdx.x;              // t = xp*20 + zp
    const int yo = blockIdx.x;               // output y-plane
    const int b  = blockIdx.y;
    const int xp = t / LLAT;
    const int zp = t - xp * LLAT;

    // Copy weight table to smem for phases 2/3 (divergent indices there).
    if (t < 2 * LLAT - 1) w2[t] = CW2[t];

    // Head of the dependency chain: the 20-deep y-column of grads.
    const float* gcol = grads + b * NPTS + xp * PLANE + zp;
    float gc[LLAT];
#pragma unroll
    for (int yp = 0; yp < LLAT; yp++) gc[yp] = gcol[yp * LLAT];

    // Epilogue operands (grads[gi] == gc[yo]; no extra load for it).
    const int gi = b * NPTS + xp * PLANE + yo * LLAT + zp;
    const float s_v = spins[gi];
    const float n_v = noise[gi];

    // Phase 1: y-reduction, weights via UNIFORM constant loads (no barrier).
    float2 a0 = make_float2(0.0f, 0.0f), a1 = make_float2(0.0f, 0.0f);
    float2 a2 = make_float2(0.0f, 0.0f), a3 = make_float2(0.0f, 0.0f);
#pragma unroll
    for (int yp = 0; yp < LLAT; yp += 4) {
        const float e0 = exp2f(-NEG2_LOG2E * fabsf(gc[yp]));
        const float e1 = exp2f(-NEG2_LOG2E * fabsf(gc[yp + 1]));
        const float e2 = exp2f(-NEG2_LOG2E * fabsf(gc[yp + 2]));
        const float e3 = exp2f(-NEG2_LOG2E * fabsf(gc[yp + 3]));
        a0 = fma2(make_float2(gc[yp] * e0, e0),
                  CW2[(LLAT - 1) + yo - yp], a0);           // uniform LDCU
        a1 = fma2(make_float2(gc[yp + 1] * e1, e1),
                  CW2[(LLAT - 1) + yo - (yp + 1)], a1);
        a2 = fma2(make_float2(gc[yp + 2] * e2, e2),
                  CW2[(LLAT - 1) + yo - (yp + 2)], a2);
        a3 = fma2(make_float2(gc[yp + 3] * e3, e3),
                  CW2[(LLAT - 1) + yo - (yp + 3)], a3);
    }
    V[t] = add2(add2(a0, a1), add2(a2, a3));

    // Precompute epilogue base while the barrier drains / MUFUs finish.
    const float base = s_v + n_v - 0.05f * gc[yo];
    __syncthreads();   // covers V and the w2 copy

    // Phase 2: z-conv. T[xp][zp] = sum_j w[zp-j] V[xp][j]
    a0 = make_float2(0.0f, 0.0f); a1 = make_float2(0.0f, 0.0f);
#pragma unroll
    for (int j = 0; j < LLAT; j += 2) {
        a0 = fma2(V[xp * LLAT + j],     w2[(LLAT - 1) + zp - j],       a0);
        a1 = fma2(V[xp * LLAT + j + 1], w2[(LLAT - 1) + zp - (j + 1)], a1);
    }
    T[t] = add2(a0, a1);
    __syncthreads();

    // Phase 3: x-conv. R[xp][zp] = sum_j w[xp-j] T[j][zp]
    a0 = make_float2(0.0f, 0.0f); a1 = make_float2(0.0f, 0.0f);
#pragma unroll
    for (int j = 0; j < LLAT; j += 2) {
        a0 = fma2(T[j * LLAT + zp],       w2[(LLAT - 1) + xp - j],       a0);
        a1 = fma2(T[(j + 1) * LLAT + zp], w2[(LLAT - 1) + xp - (j + 1)], a1);
    }
    const float2 r = add2(a0, a1);

    // Epilogue: out = base - 0.5*(u/v)
    out[gi] = base - 0.5f * __fdividef(r.x, r.y);
}

extern "C" void kernel_launch(void* const* d_in, const int* in_sizes, int n_in,
                              void* d_out, int out_size)
{
    const float* grads = (const float*)d_in[0];
    const float* spins = (const float*)d_in[1];
    // d_in[2] = pos: unused — lattice geometry is known analytically.
    const float* noise = (const float*)d_in[3];
    float* out = (float*)d_out;

    const int B = in_sizes[0] / NPTS;
    dim3 grid(LLAT, B);
    attn_opt_fused<<<grid, PLANE>>>(grads, spins, noise, out);
}

// round 10
// speedup vs baseline: 1.0036x; 1.0036x over previous
#include <cuda_runtime.h>

// AttentionOptimizer: out = spins - LR*(grads + SMOOTH*g_smooth) + noise
// g_smooth = conv3(u)/conv3(v),  u = g*exp(-BETA*|g|), v = exp(-BETA*|g|),
// separable per-axis kernel w[d] = exp(-0.0125*(d*2/19)^2) = exp(-0.05 d^2/361).
//
// R10 = R8 + safe parts of R9:
//   - grads[gi] loaded explicitly again (R9's gc[yo] dynamic register-array
//     index demoted gc[] to local memory -> 20x LDL; that was the regression)
//   - epilogue base (s + n - 0.05*g) precomputed under phase-1 latency
//   - 4 accumulators in phase 1, 2 in phases 2/3 (all constant indices)

#define LLAT 20
#define PLANE 400                 // LLAT*LLAT
#define NPTS 8000                 // LLAT^3
#define NEG2_LOG2E 2.8853900817779268f   // 2*log2(e)

// CW2[i] = {w,w} with w = exp(-0.05*(i-19)^2/361)  (hand-evaluated)
__constant__ float2 CW2[2 * LLAT - 1] = {
    {0.9512294245f, 0.9512294245f}, {0.9561166621f, 0.9561166621f},
    {0.9607628249f, 0.9607628249f}, {0.9651641734f, 0.9651641734f},
    {0.9693171397f, 0.9693171397f}, {0.9732183487f, 0.9732183487f},
    {0.9768646216f, 0.9768646216f}, {0.9802529795f, 0.9802529795f},
    {0.9833806481f, 0.9833806481f}, {0.9862450604f, 0.9862450604f},
    {0.9888438596f, 0.9888438596f}, {0.9911749058f, 0.9911749058f},
    {0.9932362740f, 0.9932362740f}, {0.9950262606f, 0.9950262606f},
    {0.9965433840f, 0.9965433840f}, {0.9977863872f, 0.9977863872f},
    {0.9987542392f, 0.9987542392f}, {0.9994461368f, 0.9994461368f},
    {0.9998615054f, 0.9998615054f}, {1.0000000000f, 1.0000000000f},
    {0.9998615054f, 0.9998615054f}, {0.9994461368f, 0.9994461368f},
    {0.9987542392f, 0.9987542392f}, {0.9977863872f, 0.9977863872f},
    {0.9965433840f, 0.9965433840f}, {0.9950262606f, 0.9950262606f},
    {0.9932362740f, 0.9932362740f}, {0.9911749058f, 0.9911749058f},
    {0.9888438596f, 0.9888438596f}, {0.9862450604f, 0.9862450604f},
    {0.9833806481f, 0.9833806481f}, {0.9802529795f, 0.9802529795f},
    {0.9768646216f, 0.9768646216f}, {0.9732183487f, 0.9732183487f},
    {0.9693171397f, 0.9693171397f}, {0.9651641734f, 0.9651641734f},
    {0.9607628249f, 0.9607628249f}, {0.9561166621f, 0.9561166621f},
    {0.9512294245f, 0.9512294245f}
};

// Packed f32x2 FMA (sm_103a): d = a*b + c on both lanes.
static __device__ __forceinline__ float2 fma2(float2 a, float2 b, float2 c) {
    float2 d;
    asm("fma.rn.f32x2 %0, %1, %2, %3;"
        : "=l"(*reinterpret_cast<unsigned long long*>(&d))
        : "l"(*reinterpret_cast<unsigned long long*>(&a)),
          "l"(*reinterpret_cast<unsigned long long*>(&b)),
          "l"(*reinterpret_cast<unsigned long long*>(&c)));
    return d;
}

static __device__ __forceinline__ float2 add2(float2 a, float2 b) {
    return make_float2(a.x + b.x, a.y + b.y);
}

__global__ void __launch_bounds__(PLANE, 1)
attn_opt_fused(const float* __restrict__ grads,
               const float* __restrict__ spins,
               const float* __restrict__ noise,
               float* __restrict__ out)
{
    __shared__ float2 V[PLANE];
    __shared__ float2 T[PLANE];
    __shared__ float2 w2[2 * LLAT - 1];   // smem copy for per-thread indices

    const int t  = threadIdx.x;              // t = xp*20 + zp
    const int yo = blockIdx.x;               // output y-plane
    const int b  = blockIdx.y;
    const int xp = t / LLAT;
    const int zp = t - xp * LLAT;

    // Copy weight table to smem for phases 2/3 (divergent indices there).
    if (t < 2 * LLAT - 1) w2[t] = CW2[t];

    // Head of the dependency chain: the 20-deep y-column of grads.
    const float* gcol = grads + b * NPTS + xp * PLANE + zp;
    float gc[LLAT];
#pragma unroll
    for (int yp = 0; yp < LLAT; yp++) gc[yp] = gcol[yp * LLAT];

    // Epilogue operands — explicit LDGs (constant-index registers only).
    const int gi = b * NPTS + xp * PLANE + yo * LLAT + zp;
    const float s_v = spins[gi];
    const float n_v = noise[gi];
    const float g_v = grads[gi];

    // Phase 1: y-reduction, weights via UNIFORM constant loads (no barrier).
    float2 a0 = make_float2(0.0f, 0.0f), a1 = make_float2(0.0f, 0.0f);
    float2 a2 = make_float2(0.0f, 0.0f), a3 = make_float2(0.0f, 0.0f);
#pragma unroll
    for (int yp = 0; yp < LLAT; yp += 4) {
        const float e0 = exp2f(-NEG2_LOG2E * fabsf(gc[yp]));
        const float e1 = exp2f(-NEG2_LOG2E * fabsf(gc[yp + 1]));
        const float e2 = exp2f(-NEG2_LOG2E * fabsf(gc[yp + 2]));
        const float e3 = exp2f(-NEG2_LOG2E * fabsf(gc[yp + 3]));
        a0 = fma2(make_float2(gc[yp] * e0, e0),
                  CW2[(LLAT - 1) + yo - yp], a0);           // uniform LDCU
        a1 = fma2(make_float2(gc[yp + 1] * e1, e1),
                  CW2[(LLAT - 1) + yo - (yp + 1)], a1);
        a2 = fma2(make_float2(gc[yp + 2] * e2, e2),
                  CW2[(LLAT - 1) + yo - (yp + 2)], a2);
        a3 = fma2(make_float2(gc[yp + 3] * e3, e3),
                  CW2[(LLAT - 1) + yo - (yp + 3)], a3);
    }
    V[t] = add2(add2(a0, a1), add2(a2, a3));

    // Precompute epilogue base while the barrier drains / MUFUs finish.
    const float base = s_v + n_v - 0.05f * g_v;
    __syncthreads();   // covers V and the w2 copy

    // Phase 2: z-conv. T[xp][zp] = sum_j w[zp-j] V[xp][j]
    a0 = make_float2(0.0f, 0.0f); a1 = make_float2(0.0f, 0.0f);
#pragma unroll
    for (int j = 0; j < LLAT; j += 2) {
        a0 = fma2(V[xp * LLAT + j],     w2[(LLAT - 1) + zp - j],       a0);
        a1 = fma2(V[xp * LLAT + j + 1], w2[(LLAT - 1) + zp - (j + 1)], a1);
    }
    T[t] = add2(a0, a1);
    __syncthreads();

    // Phase 3: x-conv. R[xp][zp] = sum_j w[xp-j] T[j][zp]
    a0 = make_float2(0.0f, 0.0f); a1 = make_float2(0.0f, 0.0f);
#pragma unroll
    for (int j = 0; j < LLAT; j += 2) {
        a0 = fma2(T[j * LLAT + zp],       w2[(LLAT - 1) + xp - j],       a0);
        a1 = fma2(T[(j + 1) * LLAT + zp], w2[(LLAT - 1) + xp - (j + 1)], a1);
    }
    const float2 r = add2(a0, a1);

    // Epilogue: out = base - 0.5*(u/v)
    out[gi] = base - 0.5f * __fdividef(r.x, r.y);
}

extern "C" void kernel_launch(void* const* d_in, const int* in_sizes, int n_in,
                              void* d_out, int out_size)
{
    const float* grads = (const float*)d_in[0];
    const float* spins = (const float*)d_in[1];
    // d_in[2] = pos: unused — lattice geometry is known analytically.
    const float* noise = (const float*)d_in[3];
    float* out = (float*)d_out;

    const int B = in_sizes[0] / NPTS;
    dim3 grid(LLAT, B);
    attn_opt_fused<<<grid, PLANE>>>(grads, spins, noise, out);
}

// round 11
// speedup vs baseline: 1.3527x; 1.3478x over previous
#include <cuda_runtime.h>

// AttentionOptimizer: out = spins - LR*(grads + SMOOTH*g_smooth) + noise
// g_smooth = conv3(u)/conv3(v),  u = g*exp(-BETA*|g|), v = exp(-BETA*|g|),
// separable per-axis kernel w[d] = exp(-0.0125*(d*2/19)^2) = exp(-0.05 d^2/361).
//
// R11 = R10 (best profiled dur: 6.37us) + two residual shaves:
//   - w2 smem copy issued FIRST so its STS drains well before the barrier
//   - epilogue store via st.global.cs (streaming; no L1 allocation at tail)
// Structure: one CTA per (b,y_out), 400 threads, constant weights (uniform
// LDCU in phase 1), smem weights for phases 2/3, 2 barriers, multi-acc FMA
// chains, packed f32x2 math throughout.

#define LLAT 20
#define PLANE 400                 // LLAT*LLAT
#define NPTS 8000                 // LLAT^3
#define NEG2_LOG2E 2.8853900817779268f   // 2*log2(e)

// CW2[i] = {w,w} with w = exp(-0.05*(i-19)^2/361)  (hand-evaluated)
__constant__ float2 CW2[2 * LLAT - 1] = {
    {0.9512294245f, 0.9512294245f}, {0.9561166621f, 0.9561166621f},
    {0.9607628249f, 0.9607628249f}, {0.9651641734f, 0.9651641734f},
    {0.9693171397f, 0.9693171397f}, {0.9732183487f, 0.9732183487f},
    {0.9768646216f, 0.9768646216f}, {0.9802529795f, 0.9802529795f},
    {0.9833806481f, 0.9833806481f}, {0.9862450604f, 0.9862450604f},
    {0.9888438596f, 0.9888438596f}, {0.9911749058f, 0.9911749058f},
    {0.9932362740f, 0.9932362740f}, {0.9950262606f, 0.9950262606f},
    {0.9965433840f, 0.9965433840f}, {0.9977863872f, 0.9977863872f},
    {0.9987542392f, 0.9987542392f}, {0.9994461368f, 0.9994461368f},
    {0.9998615054f, 0.9998615054f}, {1.0000000000f, 1.0000000000f},
    {0.9998615054f, 0.9998615054f}, {0.9994461368f, 0.9994461368f},
    {0.9987542392f, 0.9987542392f}, {0.9977863872f, 0.9977863872f},
    {0.9965433840f, 0.9965433840f}, {0.9950262606f, 0.9950262606f},
    {0.9932362740f, 0.9932362740f}, {0.9911749058f, 0.9911749058f},
    {0.9888438596f, 0.9888438596f}, {0.9862450604f, 0.9862450604f},
    {0.9833806481f, 0.9833806481f}, {0.9802529795f, 0.9802529795f},
    {0.9768646216f, 0.9768646216f}, {0.9732183487f, 0.9732183487f},
    {0.9693171397f, 0.9693171397f}, {0.9651641734f, 0.9651641734f},
    {0.9607628249f, 0.9607628249f}, {0.9561166621f, 0.9561166621f},
    {0.9512294245f, 0.9512294245f}
};

// Packed f32x2 FMA (sm_103a): d = a*b + c on both lanes.
static __device__ __forceinline__ float2 fma2(float2 a, float2 b, float2 c) {
    float2 d;
    asm("fma.rn.f32x2 %0, %1, %2, %3;"
        : "=l"(*reinterpret_cast<unsigned long long*>(&d))
        : "l"(*reinterpret_cast<unsigned long long*>(&a)),
          "l"(*reinterpret_cast<unsigned long long*>(&b)),
          "l"(*reinterpret_cast<unsigned long long*>(&c)));
    return d;
}

static __device__ __forceinline__ float2 add2(float2 a, float2 b) {
    return make_float2(a.x + b.x, a.y + b.y);
}

static __device__ __forceinline__ void stg_cs(float* p, float v) {
    asm volatile("st.global.cs.f32 [%0], %1;" :: "l"(p), "f"(v) : "memory");
}

__global__ void __launch_bounds__(PLANE, 1)
attn_opt_fused(const float* __restrict__ grads,
               const float* __restrict__ spins,
               const float* __restrict__ noise,
               float* __restrict__ out)
{
    __shared__ float2 V[PLANE];
    __shared__ float2 T[PLANE];
    __shared__ float2 w2[2 * LLAT - 1];   // smem copy for per-thread indices

    const int t  = threadIdx.x;              // t = xp*20 + zp
    const int yo = blockIdx.x;               // output y-plane
    const int b  = blockIdx.y;
    const int xp = t / LLAT;
    const int zp = t - xp * LLAT;

    // w2 copy first: STS drains long before the phase-1->2 barrier.
    if (t < 2 * LLAT - 1) w2[t] = CW2[t];

    // Head of the dependency chain: the 20-deep y-column of grads.
    const float* gcol = grads + b * NPTS + xp * PLANE + zp;
    float gc[LLAT];
#pragma unroll
    for (int yp = 0; yp < LLAT; yp++) gc[yp] = gcol[yp * LLAT];

    // Epilogue operands — explicit LDGs (constant-index registers only).
    const int gi = b * NPTS + xp * PLANE + yo * LLAT + zp;
    const float s_v = spins[gi];
    const float n_v = noise[gi];
    const float g_v = grads[gi];

    // Phase 1: y-reduction, weights via UNIFORM constant loads (no barrier).
    float2 a0 = make_float2(0.0f, 0.0f), a1 = make_float2(0.0f, 0.0f);
    float2 a2 = make_float2(0.0f, 0.0f), a3 = make_float2(0.0f, 0.0f);
#pragma unroll
    for (int yp = 0; yp < LLAT; yp += 4) {
        const float e0 = exp2f(-NEG2_LOG2E * fabsf(gc[yp]));
        const float e1 = exp2f(-NEG2_LOG2E * fabsf(gc[yp + 1]));
        const float e2 = exp2f(-NEG2_LOG2E * fabsf(gc[yp + 2]));
        const float e3 = exp2f(-NEG2_LOG2E * fabsf(gc[yp + 3]));
        a0 = fma2(make_float2(gc[yp] * e0, e0),
                  CW2[(LLAT - 1) + yo - yp], a0);           // uniform LDCU
        a1 = fma2(make_float2(gc[yp + 1] * e1, e1),
                  CW2[(LLAT - 1) + yo - (yp + 1)], a1);
        a2 = fma2(make_float2(gc[yp + 2] * e2, e2),
                  CW2[(LLAT - 1) + yo - (yp + 2)], a2);
        a3 = fma2(make_float2(gc[yp + 3] * e3, e3),
                  CW2[(LLAT - 1) + yo - (yp + 3)], a3);
    }
    V[t] = add2(add2(a0, a1), add2(a2, a3));

    // Precompute epilogue base while the barrier drains / MUFUs finish.
    const float base = s_v + n_v - 0.05f * g_v;
    __syncthreads();   // covers V and the w2 copy

    // Phase 2: z-conv. T[xp][zp] = sum_j w[zp-j] V[xp][j]
    a0 = make_float2(0.0f, 0.0f); a1 = make_float2(0.0f, 0.0f);
#pragma unroll
    for (int j = 0; j < LLAT; j += 2) {
        a0 = fma2(V[xp * LLAT + j],     w2[(LLAT - 1) + zp - j],       a0);
        a1 = fma2(V[xp * LLAT + j + 1], w2[(LLAT - 1) + zp - (j + 1)], a1);
    }
    T[t] = add2(a0, a1);
    __syncthreads();

    // Phase 3: x-conv. R[xp][zp] = sum_j w[xp-j] T[j][zp]
    a0 = make_float2(0.0f, 0.0f); a1 = make_float2(0.0f, 0.0f);
#pragma unroll
    for (int j = 0; j < LLAT; j += 2) {
        a0 = fma2(T[j * LLAT + zp],       w2[(LLAT - 1) + xp - j],       a0);
        a1 = fma2(T[(j + 1) * LLAT + zp], w2[(LLAT - 1) + xp - (j + 1)], a1);
    }
    const float2 r = add2(a0, a1);

    // Epilogue: out = base - 0.5*(u/v)  (streaming store)
    stg_cs(out + gi, base - 0.5f * __fdividef(r.x, r.y));
}

extern "C" void kernel_launch(void* const* d_in, const int* in_sizes, int n_in,
                              void* d_out, int out_size)
{
    const float* grads = (const float*)d_in[0];
    const float* spins = (const float*)d_in[1];
    // d_in[2] = pos: unused — lattice geometry is known analytically.
    const float* noise = (const float*)d_in[3];
    float* out = (float*)d_out;

    const int B = in_sizes[0] / NPTS;
    dim3 grid(LLAT, B);
    attn_opt_fused<<<grid, PLANE>>>(grads, spins, noise, out);
}